// round 10
// baseline (speedup 1.0000x reference)
#include <cuda_runtime.h>
#include <math.h>

// x, x_r : (1, 3, 32, 512, 512) float32
// size=64 -> hc=wc=32 ; 16x16 patches per frame ; t=32
// patch mean = sum(|x-x_r|)/(2*3072) ; out = log(mean_t(max_patches))
// Deferred scaling: out = log( sum_t(max_p sum|dx|) / (32*6144) )
//
// CONTIGUOUS-STREAM layout: CTA = (t, ph, half) = 16 complete 512-wide rows
// x 3 channels -> six 32KB sequential streams per CTA (vs 96x128B strided
// before). Thread's float4 column is fixed -> fixed patch-column pw; patch
// halves are joined across the CTA pair via one commutative float atomicAdd
// per patch + a per-pair release ticket. Second CTA of each pair publishes
// the 16 patch maxima (REDG); the 512th pair finalizes log(). All global
// state is re-armed every launch -> graph-replay deterministic.

#define T_DIM 32
#define NCTA 1024            // 32 t * 16 ph * 2 halves
#define NPAIR 512
#define HW 512
#define TSTRIDE (512u * 512u)
#define CSTRIDE (32u * 512u * 512u)

__device__ float        g_patch_sum[8192];   // zero-init; reset by pair's 2nd CTA
__device__ unsigned int g_pair_done[NPAIR];  // zero-init; reset by pair's 2nd CTA
__device__ int          g_frame_max[T_DIM];  // float bits (>=0); reset by final CTA
__device__ unsigned int g_done_count;        // reset by final CTA

__device__ __forceinline__ float4 ldcs4(const float* p) {
    float4 v;
    asm volatile("ld.global.cs.v4.f32 {%0,%1,%2,%3}, [%4];"
                 : "=f"(v.x), "=f"(v.y), "=f"(v.z), "=f"(v.w) : "l"(p));
    return v;
}

__global__ __launch_bounds__(256, 8)
void patch_loss_kernel(const float* __restrict__ x, const float* __restrict__ xr,
                       float* __restrict__ out) {
    const int bid  = blockIdx.x;
    const int t    = bid >> 5;
    const int ph   = (bid >> 1) & 15;
    const int half = bid & 1;
    const int tid  = threadIdx.x;

    // 256 threads cover 2 rows per step (256 float4 = 1024 floats); a thread's
    // float4-column is tid%128 (fixed) -> pw = (tid%128)/8 fixed for the CTA.
    const size_t base = (size_t)t * TSTRIDE
                      + (size_t)(ph * 32 + half * 16) * HW
                      + (size_t)tid * 4;
    const float* px = x  + base;
    const float* pr = xr + base;

    float acc = 0.0f;
    #pragma unroll
    for (int c = 0; c < 3; ++c) {
        #pragma unroll
        for (int i = 0; i < 8; ++i) {       // 8 steps x 2 rows = 16 rows
            const size_t off = (size_t)c * CSTRIDE + (size_t)i * 1024;
            const float4 a = ldcs4(px + off);
            const float4 b = ldcs4(pr + off);
            acc += fabsf(a.x - b.x) + fabsf(a.y - b.y)
                 + fabsf(a.z - b.z) + fabsf(a.w - b.w);
        }
    }

    // 8-lane segmented reduce: lanes sharing a pw (8 consecutive) sum up
    acc += __shfl_xor_sync(0xFFFFFFFFu, acc, 4);
    acc += __shfl_xor_sync(0xFFFFFFFFu, acc, 2);
    acc += __shfl_xor_sync(0xFFFFFFFFu, acc, 1);

    __shared__ float    s[16][2];   // [pw][row-of-pair slot]
    __shared__ unsigned sflag;
    const int wid = tid >> 5, lane = tid & 31;
    if (tid == 0) sflag = 0;
    if ((lane & 7) == 0) {
        const int pw = 4 * (wid & 3) + (lane >> 3);
        s[pw][wid >> 2] = acc;      // warps 0-3 -> slot 0, warps 4-7 -> slot 1
    }
    __syncthreads();

    // join halves: commutative fp add -> deterministic patch totals
    if (tid < 16) {
        const float hs = s[tid][0] + s[tid][1];
        atomicAdd(&g_patch_sum[(bid >> 1) * 16 + tid], hs);
    }
    __syncthreads();

    if (tid == 0) {
        unsigned prev;
        asm volatile("atom.release.gpu.global.add.u32 %0, [%1], 1;"
                     : "=r"(prev) : "l"(&g_pair_done[bid >> 1]) : "memory");
        if (prev == 1) {                         // second CTA of the pair
            asm volatile("fence.acq_rel.gpu;" ::: "memory");
            sflag = 1;
            g_pair_done[bid >> 1] = 0;           // re-arm pair ticket
        }
    }
    __syncthreads();

    if (sflag) {
        if (tid < 16) {
            const int p = (bid >> 1) * 16 + tid;
            const float total = __ldcg(&g_patch_sum[p]);
            g_patch_sum[p] = 0.0f;               // re-arm patch cell
            asm volatile("red.global.max.s32 [%0], %1;"
                         :: "l"(&g_frame_max[t]), "r"(__float_as_int(total)) : "memory");
        }
        __syncthreads();
        if (tid == 0) {
            unsigned prev2;
            asm volatile("atom.release.gpu.global.add.u32 %0, [%1], 1;"
                         : "=r"(prev2) : "l"(&g_done_count) : "memory");
            if (prev2 == NPAIR - 1) {            // very last pair: finalize
                asm volatile("fence.acq_rel.gpu;" ::: "memory");
                float sum = 0.0f;
                #pragma unroll
                for (int i = 0; i < T_DIM; ++i)
                    sum += __int_as_float(__ldcg(&g_frame_max[i]));
                *out = logf(sum / (32.0f * 6144.0f));
                g_done_count = 0u;               // re-arm
                #pragma unroll
                for (int i = 0; i < T_DIM; ++i) g_frame_max[i] = 0;
            }
        }
    }
}

extern "C" void kernel_launch(void* const* d_in, const int* in_sizes, int n_in,
                              void* d_out, int out_size) {
    const float* x  = (const float*)d_in[0];
    const float* xr = (const float*)d_in[1];
    patch_loss_kernel<<<NCTA, 256>>>(x, xr, (float*)d_out);
}

// round 11
// speedup vs baseline: 1.1812x; 1.1812x over previous
#include <cuda_runtime.h>
#include <math.h>

// x, x_r : (1, 3, 32, 512, 512) float32
// size=64 -> hc=wc=32 ; 16x16 patches per frame ; t=32
// patch mean = sum(|x - x_r|) / (2*3072) ; out = log(mean_t(max_patches))
// Deferred scaling: out = log( sum_t(max_p sum|dx|) / (32*6144) )
//
// Patch-per-CTA (8192 x 256, the measured-best shape) with a SOFTWARE-
// PIPELINED load schedule at occupancy 6. At occ 8 the 64K-reg file clamps
// every thread to 32 regs -> only ~2 LDG.128 in flight (measured plateau
// 5.8 TB/s). occ 6 frees 42 regs/thread; the schedule below keeps a steady
// ~4 loads outstanding (no 6-deep front burst, which regressed in R8):
//   issue a0,b0,a1,b1 ; compute c0 ; issue a2,b2 ; compute c1 ; compute c2

#define T_DIM 32
#define NPATCH 8192
#define HW 512
#define TSTRIDE (512u * 512u)
#define CSTRIDE (32u * 512u * 512u)

__device__ int          g_frame_max[T_DIM];   // float bits; >=0 so int order == float order
__device__ unsigned int g_done_count;

__device__ __forceinline__ float4 ldcs4(const float* p) {
    float4 v;
    asm volatile("ld.global.cs.v4.f32 {%0,%1,%2,%3}, [%4];"
                 : "=f"(v.x), "=f"(v.y), "=f"(v.z), "=f"(v.w) : "l"(p));
    return v;
}

__global__ __launch_bounds__(256, 6)
void patch_loss_kernel(const float* __restrict__ x, const float* __restrict__ xr,
                       float* __restrict__ out) {
    const int p  = blockIdx.x;          // t*256 + ph*16 + pw
    const int t  = p >> 8;
    const int ph = (p >> 4) & 15;
    const int pw = p & 15;

    // thread slot: row = tid/8 (0..31), col4 = (tid%8)*4 ; same for all channels
    const int row = threadIdx.x >> 3;
    const int col = (threadIdx.x & 7) << 2;
    const size_t base = (size_t)t * TSTRIDE
                      + (size_t)(ph * 32 + row) * HW
                      + (size_t)(pw * 32 + col);
    const float* px = x  + base;
    const float* pr = xr + base;

    // ---- pipelined: steady ~4 outstanding 16B loads ----
    const float4 a0 = ldcs4(px);
    const float4 b0 = ldcs4(pr);
    const float4 a1 = ldcs4(px + CSTRIDE);
    const float4 b1 = ldcs4(pr + CSTRIDE);

    float acc = fabsf(a0.x - b0.x) + fabsf(a0.y - b0.y)
              + fabsf(a0.z - b0.z) + fabsf(a0.w - b0.w);

    const float4 a2 = ldcs4(px + 2u * CSTRIDE);
    const float4 b2 = ldcs4(pr + 2u * CSTRIDE);

    acc += fabsf(a1.x - b1.x) + fabsf(a1.y - b1.y)
         + fabsf(a1.z - b1.z) + fabsf(a1.w - b1.w);
    acc += fabsf(a2.x - b2.x) + fabsf(a2.y - b2.y)
         + fabsf(a2.z - b2.z) + fabsf(a2.w - b2.w);

    // intra-warp reduce
    #pragma unroll
    for (int o = 16; o > 0; o >>= 1)
        acc += __shfl_xor_sync(0xFFFFFFFFu, acc, o);

    __shared__ float s[8];
    if ((threadIdx.x & 31) == 0) s[threadIdx.x >> 5] = acc;
    __syncthreads();

    if (threadIdx.x < 32) {
        const int lane = threadIdx.x;
        float v = (lane < 8) ? s[lane] : 0.0f;
        #pragma unroll
        for (int o = 16; o > 0; o >>= 1)
            v += __shfl_xor_sync(0xFFFFFFFFu, v, o);   // lane-uniform block total

        unsigned int prev = 0;
        if (lane == 0) {
            // REDG max (no return), L2-side
            asm volatile("red.global.max.s32 [%0], %1;"
                         :: "l"(&g_frame_max[t]), "r"(__float_as_int(v)) : "memory");
            // release-ordered ticket: orders the red above, no L1-flushing fence
            asm volatile("atom.release.gpu.global.add.u32 %0, [%1], 1;"
                         : "=r"(prev) : "l"(&g_done_count) : "memory");
        }
        prev = __shfl_sync(0xFFFFFFFFu, prev, 0);

        if (prev == NPATCH - 1) {                       // last CTA: finalize
            asm volatile("fence.acq_rel.gpu;" ::: "memory");
            float sum = __int_as_float(__ldcg(&g_frame_max[lane]));
            #pragma unroll
            for (int o = 16; o > 0; o >>= 1)
                sum += __shfl_xor_sync(0xFFFFFFFFu, sum, o);
            if (lane == 0) {
                *out = logf(sum / (32.0f * 6144.0f));
                g_done_count = 0u;                      // re-arm for next replay
            }
            __syncwarp();
            g_frame_max[lane] = 0;                      // re-arm (after reads)
        }
    }
}

extern "C" void kernel_launch(void* const* d_in, const int* in_sizes, int n_in,
                              void* d_out, int out_size) {
    const float* x  = (const float*)d_in[0];
    const float* xr = (const float*)d_in[1];
    patch_loss_kernel<<<NPATCH, 256>>>(x, xr, (float*)d_out);
}